// round 1
// baseline (speedup 1.0000x reference)
#include <cuda_runtime.h>
#include <math.h>

// ---------------- problem constants ----------------
#define NROWS 25000
#define NQ    8000
#define XD    100
#define YD    120
#define HID   100
#define KPA   128   // padded K for fx mismatch (K=120)
#define KPB   112   // padded K for gy mismatch (K=100)

// ---------------- scratch (static device globals; no allocation) -------------
__device__ float g_h   [NROWS * HID];   // hidden scratch (reused serially)
__device__ float g_xmap[NROWS * YD];
__device__ float g_ymap[NROWS * XD];
__device__ float g_xrt [NROWS * XD];
__device__ float g_yrt [NROWS * YD];
__device__ float g_qAT [KPA * NQ];      // x_mapped[x_idx] transposed [KP][NQ]
__device__ float g_qBT [KPB * NQ];      // y_mapped[y_idx] transposed
__device__ float g_qnA [NQ];
__device__ float g_qnB [NQ];
__device__ float g_tnY [NROWS];
__device__ float g_tnX [NROWS];
__device__ unsigned long long g_keyA[NQ];
__device__ unsigned long long g_keyB[NQ];

// ---------------- init ----------------
__global__ void k_init(float* out) {
    int i = blockIdx.x * blockDim.x + threadIdx.x;
    if (i == 0) out[0] = 0.0f;
    if (i < NQ) { g_keyA[i] = ~0ULL; g_keyB[i] = ~0ULL; }
}

// ---------------- generic SGEMM with bias (+optional relu) -------------------
// C[M,N] = A[M,K] @ B[K,N] + bias ; block tile 64x64, thread tile 4x4.
#define GBM 64
#define GBN 64
#define GBK 16
__global__ __launch_bounds__(256)
void k_gemm(const float* __restrict__ A, const float* __restrict__ B,
            const float* __restrict__ bias, float* __restrict__ C,
            int M, int N, int K, int relu)
{
    __shared__ float As[GBK][GBM + 1];  // +1 pad: avoid bank conflicts on store
    __shared__ float Bs[GBK][GBN];
    int tid = threadIdx.x;
    int tx = tid & 15, ty = tid >> 4;
    int m0 = blockIdx.x * GBM, n0 = blockIdx.y * GBN;
    float acc[4][4] = {};

    for (int k0 = 0; k0 < K; k0 += GBK) {
#pragma unroll
        for (int i = 0; i < 4; i++) {
            int lin = tid + i * 256;
            int m = lin >> 4, k = lin & 15;
            int gm = m0 + m, gk = k0 + k;
            As[k][m] = (gm < M && gk < K) ? A[(size_t)gm * K + gk] : 0.0f;
        }
#pragma unroll
        for (int i = 0; i < 4; i++) {
            int lin = tid + i * 256;
            int k = lin >> 6, n = lin & 63;
            int gk = k0 + k, gn = n0 + n;
            Bs[k][n] = (gk < K && gn < N) ? B[(size_t)gk * N + gn] : 0.0f;
        }
        __syncthreads();
#pragma unroll
        for (int kk = 0; kk < GBK; kk++) {
            float a[4], b[4];
#pragma unroll
            for (int i = 0; i < 4; i++) a[i] = As[kk][ty * 4 + i];
#pragma unroll
            for (int j = 0; j < 4; j++) b[j] = Bs[kk][tx * 4 + j];
#pragma unroll
            for (int i = 0; i < 4; i++)
#pragma unroll
                for (int j = 0; j < 4; j++)
                    acc[i][j] = fmaf(a[i], b[j], acc[i][j]);
        }
        __syncthreads();
    }
#pragma unroll
    for (int i = 0; i < 4; i++) {
        int gm = m0 + ty * 4 + i;
        if (gm >= M) continue;
#pragma unroll
        for (int j = 0; j < 4; j++) {
            int gn = n0 + tx * 4 + j;
            if (gn >= N) continue;
            float v = acc[i][j] + bias[gn];
            if (relu) v = fmaxf(v, 0.0f);
            C[(size_t)gm * N + gn] = v;
        }
    }
}

// ---------------- mean of row norms of (A - B), scaled, atomic into out ------
__global__ void k_rownorm_diff(const float* __restrict__ A, const float* __restrict__ B,
                               int M, int Kc, float scale, float* out)
{
    int w = threadIdx.x >> 5, lane = threadIdx.x & 31;
    int row = blockIdx.x * 8 + w;
    float r = 0.0f;
    if (row < M) {
        const float* a = A + (size_t)row * Kc;
        const float* b = B + (size_t)row * Kc;
        float s = 0.0f;
        for (int j = lane; j < Kc; j += 32) { float d = a[j] - b[j]; s = fmaf(d, d, s); }
#pragma unroll
        for (int o = 16; o; o >>= 1) s += __shfl_xor_sync(0xffffffffu, s, o);
        r = sqrtf(s);
    }
    __shared__ float sh[8];
    if (lane == 0) sh[w] = r;
    __syncthreads();
    if (threadIdx.x == 0) {
        float t = 0.0f;
#pragma unroll
        for (int i = 0; i < 8; i++) t += sh[i];
        atomicAdd(out, t * scale);
    }
}

// sup terms: mean_i || A[imap[2i+aSel]] - B[imap[2i+1-aSel]] ||
__global__ void k_rownorm_sup(const float* __restrict__ A, const float* __restrict__ B,
                              const int* __restrict__ imap, int Kc, int aSel,
                              float scale, float* out)
{
    int w = threadIdx.x >> 5, lane = threadIdx.x & 31;
    int i = blockIdx.x * 8 + w;
    float r = 0.0f;
    if (i < NQ) {
        int ra = imap[2 * i + aSel];
        int rb = imap[2 * i + 1 - aSel];
        const float* a = A + (size_t)ra * Kc;
        const float* b = B + (size_t)rb * Kc;
        float s = 0.0f;
        for (int j = lane; j < Kc; j += 32) { float d = a[j] - b[j]; s = fmaf(d, d, s); }
#pragma unroll
        for (int o = 16; o; o >>= 1) s += __shfl_xor_sync(0xffffffffu, s, o);
        r = sqrtf(s);
    }
    __shared__ float sh[8];
    if (lane == 0) sh[w] = r;
    __syncthreads();
    if (threadIdx.x == 0) {
        float t = 0.0f;
#pragma unroll
        for (int i2 = 0; i2 < 8; i2++) t += sh[i2];
        atomicAdd(out, t * scale);
    }
}

// ---------------- squared row norms of target matrix -------------------------
__global__ void k_tnorm(const float* __restrict__ T, int M, int Kc, float* __restrict__ tn)
{
    int w = threadIdx.x >> 5, lane = threadIdx.x & 31;
    int row = blockIdx.x * 8 + w;
    if (row >= M) return;
    const float* a = T + (size_t)row * Kc;
    float s = 0.0f;
    for (int j = lane; j < Kc; j += 32) s = fmaf(a[j], a[j], s);
#pragma unroll
    for (int o = 16; o; o >>= 1) s += __shfl_xor_sync(0xffffffffu, s, o);
    if (lane == 0) tn[row] = s;
}

// ---------------- gather queries (transposed + padded) + query sq norms ------
__global__ void k_gather(const float* __restrict__ src, const int* __restrict__ imap,
                         int sel, int Kc, int KP, float* __restrict__ QT,
                         float* __restrict__ qn)
{
    int w = threadIdx.x >> 5, lane = threadIdx.x & 31;
    int i = blockIdx.x * 8 + w;
    if (i >= NQ) return;
    int r = imap[2 * i + sel];
    const float* a = src + (size_t)r * Kc;
    float s = 0.0f;
    for (int k = lane; k < KP; k += 32) {
        float v = (k < Kc) ? a[k] : 0.0f;
        QT[(size_t)k * NQ + i] = v;
        s = fmaf(v, v, s);
    }
#pragma unroll
    for (int o = 16; o; o >>= 1) s += __shfl_xor_sync(0xffffffffu, s, o);
    if (lane == 0) qn[i] = s;
}

// ---------------- 1-NN distance GEMM ----------------
// Block: 64 queries x 128-target tiles over a target chunk. 128 threads, 8x8 regs.
// key = (bits(max(d2,0)) << 32) | target_idx  -> min key == (min d2, lowest idx)
#define MQ 64
#define MT 128
#define MK 16
__global__ __launch_bounds__(128, 4)
void k_mismatch(const float* __restrict__ QT,  // [KP][NQ]
                const float* __restrict__ qn,  // [NQ]
                const float* __restrict__ T,   // [NT][K] row-major
                const float* __restrict__ tn,  // [NT]
                unsigned long long* __restrict__ keys,
                int NT, int K, int KP)
{
    __shared__ float Qs[KPA][MQ];      // 32 KB (KP <= 128)
    __shared__ float Ts[MK][MT];       // 8 KB
    __shared__ float Tns[MT];
    __shared__ unsigned long long red[MQ];

    int tid = threadIdx.x;
    int tx = tid & 15;     // 16 target-groups of 8
    int ty = tid >> 4;     // 8 query-groups of 8
    int q0 = blockIdx.x * MQ;

    // load full query tile [KP][64] once
    for (int lin = tid; lin < KP * MQ; lin += 128) {
        int k = lin >> 6, q = lin & 63;
        Qs[k][q] = QT[(size_t)k * NQ + q0 + q];
    }

    float qnr[8];
#pragma unroll
    for (int i = 0; i < 8; i++) qnr[i] = qn[q0 + ty * 8 + i];

    unsigned long long best[8];
#pragma unroll
    for (int i = 0; i < 8; i++) best[i] = ~0ULL;

    int chunk = (NT + gridDim.y - 1) / gridDim.y;
    int tStart = blockIdx.y * chunk;
    int tEnd = min(NT, tStart + chunk);

    __syncthreads();

    for (int t0 = tStart; t0 < tEnd; t0 += MT) {
        int tmine = t0 + tid;
        Tns[tid] = (tmine < tEnd) ? tn[tmine] : 0.0f;

        float acc[8][8];
#pragma unroll
        for (int i = 0; i < 8; i++)
#pragma unroll
            for (int j = 0; j < 8; j++) acc[i][j] = 0.0f;

        for (int ks = 0; ks < KP; ks += MK) {
            // each thread loads 16 consecutive k of target row (t0+tid)
            {
                bool tok = (tmine < tEnd);
                const float* trow = T + (size_t)tmine * K + ks;
                if (tok && (ks + MK) <= K) {
#pragma unroll
                    for (int v4 = 0; v4 < 4; v4++) {
                        float4 v = *(const float4*)(trow + v4 * 4);
                        Ts[v4 * 4 + 0][tid] = v.x;
                        Ts[v4 * 4 + 1][tid] = v.y;
                        Ts[v4 * 4 + 2][tid] = v.z;
                        Ts[v4 * 4 + 3][tid] = v.w;
                    }
                } else {
#pragma unroll
                    for (int kk = 0; kk < MK; kk++)
                        Ts[kk][tid] = (tok && (ks + kk) < K) ? trow[kk] : 0.0f;
                }
            }
            __syncthreads();
#pragma unroll
            for (int kk = 0; kk < MK; kk++) {
                float a[8], b[8];
#pragma unroll
                for (int i = 0; i < 8; i++) a[i] = Qs[ks + kk][ty * 8 + i];
#pragma unroll
                for (int j = 0; j < 8; j++) b[j] = Ts[kk][tx * 8 + j];
#pragma unroll
                for (int i = 0; i < 8; i++)
#pragma unroll
                    for (int j = 0; j < 8; j++)
                        acc[i][j] = fmaf(a[i], b[j], acc[i][j]);
            }
            __syncthreads();
        }
        // epilogue: d2 = |q|^2 + |t|^2 - 2 q.t, clamp, fold into best key
#pragma unroll
        for (int j = 0; j < 8; j++) {
            int t = t0 + tx * 8 + j;
            if (t < tEnd) {
                float tnv = Tns[tx * 8 + j];
#pragma unroll
                for (int i = 0; i < 8; i++) {
                    float d2 = fmaxf(qnr[i] + tnv - 2.0f * acc[i][j], 0.0f);
                    unsigned long long key =
                        ((unsigned long long)__float_as_uint(d2) << 32) | (unsigned int)t;
                    if (key < best[i]) best[i] = key;
                }
            }
        }
        __syncthreads();  // protect Tns before next tile's overwrite
    }

    // cross-thread reduce (16 tx threads share each query) then one global atomic
    if (tid < MQ) red[tid] = ~0ULL;
    __syncthreads();
#pragma unroll
    for (int i = 0; i < 8; i++) atomicMin(&red[ty * 8 + i], best[i]);
    __syncthreads();
    if (tid < MQ) atomicMin(&keys[q0 + tid], red[tid]);
}

// ---------------- finalize mismatch terms ----------------
__global__ void k_finish(const unsigned long long* __restrict__ keys,
                         const int* __restrict__ imap, int sel, float scale, float* out)
{
    __shared__ float sh[256];
    int i = blockIdx.x * blockDim.x + threadIdx.x;
    float c = 0.0f;
    if (i < NQ) {
        unsigned long long k = keys[i];
        float d2 = __uint_as_float((unsigned int)(k >> 32));
        int nn = (int)(unsigned int)(k & 0xffffffffu);
        float v = sqrtf(d2);
        if (nn != imap[2 * i + sel]) c = ceilf(v) - floorf(v);
    }
    sh[threadIdx.x] = c;
    __syncthreads();
    for (int s = 128; s; s >>= 1) {
        if (threadIdx.x < s) sh[threadIdx.x] += sh[threadIdx.x + s];
        __syncthreads();
    }
    if (threadIdx.x == 0) atomicAdd(out, sh[0] * scale);
}

// ---------------- host orchestration ----------------
extern "C" void kernel_launch(void* const* d_in, const int* in_sizes, int n_in,
                              void* d_out, int out_size)
{
    const float* x_w   = (const float*)d_in[0];
    const float* y_w   = (const float*)d_in[1];
    const float* fx_w1 = (const float*)d_in[2];
    const float* fx_b1 = (const float*)d_in[3];
    const float* fx_w2 = (const float*)d_in[4];
    const float* fx_b2 = (const float*)d_in[5];
    const float* gy_w1 = (const float*)d_in[6];
    const float* gy_b1 = (const float*)d_in[7];
    const float* gy_w2 = (const float*)d_in[8];
    const float* gy_b2 = (const float*)d_in[9];
    const int*   imap  = (const int*)d_in[10];
    float* out = (float*)d_out;

    float *h, *xmap, *ymap, *xrt, *yrt, *qAT, *qBT, *qnA, *qnB, *tnY, *tnX;
    unsigned long long *keyA, *keyB;
    cudaGetSymbolAddress((void**)&h,    g_h);
    cudaGetSymbolAddress((void**)&xmap, g_xmap);
    cudaGetSymbolAddress((void**)&ymap, g_ymap);
    cudaGetSymbolAddress((void**)&xrt,  g_xrt);
    cudaGetSymbolAddress((void**)&yrt,  g_yrt);
    cudaGetSymbolAddress((void**)&qAT,  g_qAT);
    cudaGetSymbolAddress((void**)&qBT,  g_qBT);
    cudaGetSymbolAddress((void**)&qnA,  g_qnA);
    cudaGetSymbolAddress((void**)&qnB,  g_qnB);
    cudaGetSymbolAddress((void**)&tnY,  g_tnY);
    cudaGetSymbolAddress((void**)&tnX,  g_tnX);
    cudaGetSymbolAddress((void**)&keyA, g_keyA);
    cudaGetSymbolAddress((void**)&keyB, g_keyB);

    k_init<<<(NQ + 255) / 256, 256>>>(out);

    dim3 gg((NROWS + GBM - 1) / GBM, 2);  // N=100/120 both need 2 col-blocks
    // x_mapped = relu(x@fx_w1+b1)@fx_w2+b2
    k_gemm<<<gg, 256>>>(x_w, fx_w1, fx_b1, h,    NROWS, HID, XD,  1);
    k_gemm<<<gg, 256>>>(h,   fx_w2, fx_b2, xmap, NROWS, YD,  HID, 0);
    // y_mapped = relu(y@gy_w1+b1)@gy_w2+b2
    k_gemm<<<gg, 256>>>(y_w, gy_w1, gy_b1, h,    NROWS, HID, YD,  1);
    k_gemm<<<gg, 256>>>(h,   gy_w2, gy_b2, ymap, NROWS, XD,  HID, 0);
    // x_rt = gy(x_mapped)
    k_gemm<<<gg, 256>>>(xmap, gy_w1, gy_b1, h,   NROWS, HID, YD,  1);
    k_gemm<<<gg, 256>>>(h,    gy_w2, gy_b2, xrt, NROWS, XD,  HID, 0);
    // y_rt = fx(y_mapped)
    k_gemm<<<gg, 256>>>(ymap, fx_w1, fx_b1, h,   NROWS, HID, XD,  1);
    k_gemm<<<gg, 256>>>(h,    fx_w2, fx_b2, yrt, NROWS, YD,  HID, 0);

    // cycle terms
    k_rownorm_diff<<<(NROWS + 7) / 8, 256>>>(xrt, x_w, NROWS, XD, 1.0f / NROWS, out);
    k_rownorm_diff<<<(NROWS + 7) / 8, 256>>>(yrt, y_w, NROWS, YD, 1.0f / NROWS, out);
    // sup terms
    k_rownorm_sup<<<(NQ + 7) / 8, 256>>>(xmap, y_w, imap, YD, 0, 1.0f / NQ, out);
    k_rownorm_sup<<<(NQ + 7) / 8, 256>>>(ymap, x_w, imap, XD, 1, 1.0f / NQ, out);

    // 1-NN prep
    k_tnorm<<<(NROWS + 7) / 8, 256>>>(y_w, NROWS, YD, tnY);
    k_tnorm<<<(NROWS + 7) / 8, 256>>>(x_w, NROWS, XD, tnX);
    k_gather<<<(NQ + 7) / 8, 256>>>(xmap, imap, 0, YD, KPA, qAT, qnA);
    k_gather<<<(NQ + 7) / 8, 256>>>(ymap, imap, 1, XD, KPB, qBT, qnB);

    // 1-NN distance GEMMs (query tiles x target chunks)
    dim3 mg(NQ / MQ, 8);  // 125 x 8 = 1000 blocks
    k_mismatch<<<mg, 128>>>(qAT, qnA, y_w, tnY, keyA, NROWS, YD, KPA);
    k_mismatch<<<mg, 128>>>(qBT, qnB, x_w, tnX, keyB, NROWS, XD, KPB);

    k_finish<<<(NQ + 255) / 256, 256>>>(keyA, imap, 0, 1.0f / NQ, out);
    k_finish<<<(NQ + 255) / 256, 256>>>(keyB, imap, 1, 1.0f / NQ, out);
}

// round 2
// speedup vs baseline: 1.0264x; 1.0264x over previous
#include <cuda_runtime.h>
#include <math.h>

// ---------------- problem constants ----------------
#define NROWS 25000
#define NQ    8000
#define XD    100
#define YD    120
#define HID   100
#define KPA   128   // padded K for fx mismatch (K=120)
#define KPB   112   // padded K for gy mismatch (K=100)

// ---------------- scratch (static device globals; no allocation) -------------
__device__ float g_h   [NROWS * HID];
__device__ float g_xmap[NROWS * YD];
__device__ float g_ymap[NROWS * XD];
__device__ float g_xrt [NROWS * XD];
__device__ float g_yrt [NROWS * YD];
__device__ float g_qAT [KPA * NQ];
__device__ float g_qBT [KPB * NQ];
__device__ float g_qnA [NQ];
__device__ float g_qnB [NQ];
__device__ float g_tnY [NROWS];
__device__ float g_tnX [NROWS];
__device__ unsigned long long g_keyA[NQ];
__device__ unsigned long long g_keyB[NQ];

// ---------------- init ----------------
__global__ void k_init(float* out) {
    int i = blockIdx.x * blockDim.x + threadIdx.x;
    if (i == 0) out[0] = 0.0f;
    if (i < NQ) { g_keyA[i] = ~0ULL; g_keyB[i] = ~0ULL; }
}

// ---------------- generic SGEMM with bias (+optional relu) -------------------
#define GBM 64
#define GBN 64
#define GBK 16
__global__ __launch_bounds__(256)
void k_gemm(const float* __restrict__ A, const float* __restrict__ B,
            const float* __restrict__ bias, float* __restrict__ C,
            int M, int N, int K, int relu)
{
    __shared__ float As[GBK][GBM + 1];
    __shared__ float Bs[GBK][GBN];
    int tid = threadIdx.x;
    int tx = tid & 15, ty = tid >> 4;
    int m0 = blockIdx.x * GBM, n0 = blockIdx.y * GBN;
    float acc[4][4] = {};

    for (int k0 = 0; k0 < K; k0 += GBK) {
#pragma unroll
        for (int i = 0; i < 4; i++) {
            int lin = tid + i * 256;
            int m = lin >> 4, k = lin & 15;
            int gm = m0 + m, gk = k0 + k;
            As[k][m] = (gm < M && gk < K) ? A[(size_t)gm * K + gk] : 0.0f;
        }
#pragma unroll
        for (int i = 0; i < 4; i++) {
            int lin = tid + i * 256;
            int k = lin >> 6, n = lin & 63;
            int gk = k0 + k, gn = n0 + n;
            Bs[k][n] = (gk < K && gn < N) ? B[(size_t)gk * N + gn] : 0.0f;
        }
        __syncthreads();
#pragma unroll
        for (int kk = 0; kk < GBK; kk++) {
            float a[4], b[4];
#pragma unroll
            for (int i = 0; i < 4; i++) a[i] = As[kk][ty * 4 + i];
#pragma unroll
            for (int j = 0; j < 4; j++) b[j] = Bs[kk][tx * 4 + j];
#pragma unroll
            for (int i = 0; i < 4; i++)
#pragma unroll
                for (int j = 0; j < 4; j++)
                    acc[i][j] = fmaf(a[i], b[j], acc[i][j]);
        }
        __syncthreads();
    }
#pragma unroll
    for (int i = 0; i < 4; i++) {
        int gm = m0 + ty * 4 + i;
        if (gm >= M) continue;
#pragma unroll
        for (int j = 0; j < 4; j++) {
            int gn = n0 + tx * 4 + j;
            if (gn >= N) continue;
            float v = acc[i][j] + bias[gn];
            if (relu) v = fmaxf(v, 0.0f);
            C[(size_t)gm * N + gn] = v;
        }
    }
}

// ---------------- mean of row norms of (A - B) -------------------------------
__global__ void k_rownorm_diff(const float* __restrict__ A, const float* __restrict__ B,
                               int M, int Kc, float scale, float* out)
{
    int w = threadIdx.x >> 5, lane = threadIdx.x & 31;
    int row = blockIdx.x * 8 + w;
    float r = 0.0f;
    if (row < M) {
        const float* a = A + (size_t)row * Kc;
        const float* b = B + (size_t)row * Kc;
        float s = 0.0f;
        for (int j = lane; j < Kc; j += 32) { float d = a[j] - b[j]; s = fmaf(d, d, s); }
#pragma unroll
        for (int o = 16; o; o >>= 1) s += __shfl_xor_sync(0xffffffffu, s, o);
        r = sqrtf(s);
    }
    __shared__ float sh[8];
    if (lane == 0) sh[w] = r;
    __syncthreads();
    if (threadIdx.x == 0) {
        float t = 0.0f;
#pragma unroll
        for (int i = 0; i < 8; i++) t += sh[i];
        atomicAdd(out, t * scale);
    }
}

__global__ void k_rownorm_sup(const float* __restrict__ A, const float* __restrict__ B,
                              const int* __restrict__ imap, int Kc, int aSel,
                              float scale, float* out)
{
    int w = threadIdx.x >> 5, lane = threadIdx.x & 31;
    int i = blockIdx.x * 8 + w;
    float r = 0.0f;
    if (i < NQ) {
        int ra = imap[2 * i + aSel];
        int rb = imap[2 * i + 1 - aSel];
        const float* a = A + (size_t)ra * Kc;
        const float* b = B + (size_t)rb * Kc;
        float s = 0.0f;
        for (int j = lane; j < Kc; j += 32) { float d = a[j] - b[j]; s = fmaf(d, d, s); }
#pragma unroll
        for (int o = 16; o; o >>= 1) s += __shfl_xor_sync(0xffffffffu, s, o);
        r = sqrtf(s);
    }
    __shared__ float sh[8];
    if (lane == 0) sh[w] = r;
    __syncthreads();
    if (threadIdx.x == 0) {
        float t = 0.0f;
#pragma unroll
        for (int i2 = 0; i2 < 8; i2++) t += sh[i2];
        atomicAdd(out, t * scale);
    }
}

// ---------------- squared row norms of target matrix -------------------------
__global__ void k_tnorm(const float* __restrict__ T, int M, int Kc, float* __restrict__ tn)
{
    int w = threadIdx.x >> 5, lane = threadIdx.x & 31;
    int row = blockIdx.x * 8 + w;
    if (row >= M) return;
    const float* a = T + (size_t)row * Kc;
    float s = 0.0f;
    for (int j = lane; j < Kc; j += 32) s = fmaf(a[j], a[j], s);
#pragma unroll
    for (int o = 16; o; o >>= 1) s += __shfl_xor_sync(0xffffffffu, s, o);
    if (lane == 0) tn[row] = s;
}

// ---------------- gather queries (transposed + padded) + query sq norms ------
__global__ void k_gather(const float* __restrict__ src, const int* __restrict__ imap,
                         int sel, int Kc, int KP, float* __restrict__ QT,
                         float* __restrict__ qn)
{
    int w = threadIdx.x >> 5, lane = threadIdx.x & 31;
    int i = blockIdx.x * 8 + w;
    if (i >= NQ) return;
    int r = imap[2 * i + sel];
    const float* a = src + (size_t)r * Kc;
    float s = 0.0f;
    for (int k = lane; k < KP; k += 32) {
        float v = (k < Kc) ? a[k] : 0.0f;
        QT[(size_t)k * NQ + i] = v;
        s = fmaf(v, v, s);
    }
#pragma unroll
    for (int o = 16; o; o >>= 1) s += __shfl_xor_sync(0xffffffffu, s, o);
    if (lane == 0) qn[i] = s;
}

// ---------------- 1-NN distance GEMM (packed fma.rn.f32x2 mainloop) ----------
// Block: 64 queries x 128-target tiles. 128 threads. Register tile: 8 queries
// (4 x f32x2 pairs along i) x 8 targets per thread.
#define MQ 64
#define MT 128
#define MK 16
__global__ __launch_bounds__(128, 4)
void k_mismatch(const float* __restrict__ QT,  // [KP][NQ]
                const float* __restrict__ qn,  // [NQ]
                const float* __restrict__ T,   // [NT][K] row-major
                const float* __restrict__ tn,  // [NT]
                unsigned long long* __restrict__ keys,
                int NT, int K, int KP)
{
    __shared__ float Qs[KPA][MQ];      // 32 KB
    __shared__ float Ts[MK][MT];       // 8 KB
    __shared__ float Tns[MT];
    __shared__ unsigned long long red[MQ];

    int tid = threadIdx.x;
    int tx = tid & 15;     // 16 target-groups of 8
    int ty = tid >> 4;     // 8 query-groups of 8
    int q0 = blockIdx.x * MQ;

    for (int lin = tid; lin < KP * MQ; lin += 128) {
        int k = lin >> 6, q = lin & 63;
        Qs[k][q] = QT[(size_t)k * NQ + q0 + q];
    }

    float qnr[8];
#pragma unroll
    for (int i = 0; i < 8; i++) qnr[i] = qn[q0 + ty * 8 + i];

    unsigned long long best[8];
#pragma unroll
    for (int i = 0; i < 8; i++) best[i] = ~0ULL;

    int chunk = (NT + gridDim.y - 1) / gridDim.y;
    int tStart = blockIdx.y * chunk;
    int tEnd = min(NT, tStart + chunk);

    __syncthreads();

    for (int t0 = tStart; t0 < tEnd; t0 += MT) {
        int tmine = t0 + tid;
        Tns[tid] = (tmine < tEnd) ? tn[tmine] : 0.0f;

        // acc2[ip][j]: f32x2 pair over queries (2ip, 2ip+1) for target j
        unsigned long long acc2[4][8];
#pragma unroll
        for (int ip = 0; ip < 4; ip++)
#pragma unroll
            for (int j = 0; j < 8; j++) acc2[ip][j] = 0ULL;

        for (int ks = 0; ks < KP; ks += MK) {
            {
                bool tok = (tmine < tEnd);
                const float* trow = T + (size_t)tmine * K + ks;
                if (tok && (ks + MK) <= K) {
#pragma unroll
                    for (int v4 = 0; v4 < 4; v4++) {
                        float4 v = *(const float4*)(trow + v4 * 4);
                        Ts[v4 * 4 + 0][tid] = v.x;
                        Ts[v4 * 4 + 1][tid] = v.y;
                        Ts[v4 * 4 + 2][tid] = v.z;
                        Ts[v4 * 4 + 3][tid] = v.w;
                    }
                } else {
#pragma unroll
                    for (int kk = 0; kk < MK; kk++)
                        Ts[kk][tid] = (tok && (ks + kk) < K) ? trow[kk] : 0.0f;
                }
            }
            __syncthreads();
#pragma unroll
            for (int kk = 0; kk < MK; kk++) {
                // 4 query-pairs as 64-bit loads (Qs row is 256B-aligned)
                const unsigned long long* qrow =
                    (const unsigned long long*)&Qs[ks + kk][ty * 8];
                unsigned long long a2[4];
                a2[0] = qrow[0]; a2[1] = qrow[1]; a2[2] = qrow[2]; a2[3] = qrow[3];
                // 8 target scalars, duplicated into both f32x2 halves
                float4 bv0 = *(const float4*)&Ts[kk][tx * 8];
                float4 bv1 = *(const float4*)&Ts[kk][tx * 8 + 4];
                float bf[8] = {bv0.x, bv0.y, bv0.z, bv0.w, bv1.x, bv1.y, bv1.z, bv1.w};
                unsigned long long bd[8];
#pragma unroll
                for (int j = 0; j < 8; j++)
                    asm("mov.b64 %0, {%1, %1};" : "=l"(bd[j]) : "f"(bf[j]));
#pragma unroll
                for (int ip = 0; ip < 4; ip++)
#pragma unroll
                    for (int j = 0; j < 8; j++)
                        asm("fma.rn.f32x2 %0, %1, %2, %0;"
                            : "+l"(acc2[ip][j]) : "l"(a2[ip]), "l"(bd[j]));
            }
            __syncthreads();
        }
        // epilogue: d2 = |q|^2 + |t|^2 - 2 q.t, clamp, fold into best key
#pragma unroll
        for (int j = 0; j < 8; j++) {
            int t = t0 + tx * 8 + j;
            if (t < tEnd) {
                float tnv = Tns[tx * 8 + j];
#pragma unroll
                for (int ip = 0; ip < 4; ip++) {
                    float lo, hi;
                    asm("mov.b64 {%0, %1}, %2;" : "=f"(lo), "=f"(hi) : "l"(acc2[ip][j]));
                    float d2lo = fmaxf(qnr[2 * ip] + tnv - 2.0f * lo, 0.0f);
                    float d2hi = fmaxf(qnr[2 * ip + 1] + tnv - 2.0f * hi, 0.0f);
                    unsigned long long klo =
                        ((unsigned long long)__float_as_uint(d2lo) << 32) | (unsigned int)t;
                    unsigned long long khi =
                        ((unsigned long long)__float_as_uint(d2hi) << 32) | (unsigned int)t;
                    if (klo < best[2 * ip]) best[2 * ip] = klo;
                    if (khi < best[2 * ip + 1]) best[2 * ip + 1] = khi;
                }
            }
        }
        __syncthreads();  // protect Tns before next tile's overwrite
    }

    if (tid < MQ) red[tid] = ~0ULL;
    __syncthreads();
#pragma unroll
    for (int i = 0; i < 8; i++) atomicMin(&red[ty * 8 + i], best[i]);
    __syncthreads();
    if (tid < MQ) atomicMin(&keys[q0 + tid], red[tid]);
}

// ---------------- finalize mismatch terms ----------------
__global__ void k_finish(const unsigned long long* __restrict__ keys,
                         const int* __restrict__ imap, int sel, float scale, float* out)
{
    __shared__ float sh[256];
    int i = blockIdx.x * blockDim.x + threadIdx.x;
    float c = 0.0f;
    if (i < NQ) {
        unsigned long long k = keys[i];
        float d2 = __uint_as_float((unsigned int)(k >> 32));
        int nn = (int)(unsigned int)(k & 0xffffffffu);
        float v = sqrtf(d2);
        if (nn != imap[2 * i + sel]) c = ceilf(v) - floorf(v);
    }
    sh[threadIdx.x] = c;
    __syncthreads();
    for (int s = 128; s; s >>= 1) {
        if (threadIdx.x < s) sh[threadIdx.x] += sh[threadIdx.x + s];
        __syncthreads();
    }
    if (threadIdx.x == 0) atomicAdd(out, sh[0] * scale);
}

// ---------------- host orchestration ----------------
extern "C" void kernel_launch(void* const* d_in, const int* in_sizes, int n_in,
                              void* d_out, int out_size)
{
    const float* x_w   = (const float*)d_in[0];
    const float* y_w   = (const float*)d_in[1];
    const float* fx_w1 = (const float*)d_in[2];
    const float* fx_b1 = (const float*)d_in[3];
    const float* fx_w2 = (const float*)d_in[4];
    const float* fx_b2 = (const float*)d_in[5];
    const float* gy_w1 = (const float*)d_in[6];
    const float* gy_b1 = (const float*)d_in[7];
    const float* gy_w2 = (const float*)d_in[8];
    const float* gy_b2 = (const float*)d_in[9];
    const int*   imap  = (const int*)d_in[10];
    float* out = (float*)d_out;

    float *h, *xmap, *ymap, *xrt, *yrt, *qAT, *qBT, *qnA, *qnB, *tnY, *tnX;
    unsigned long long *keyA, *keyB;
    cudaGetSymbolAddress((void**)&h,    g_h);
    cudaGetSymbolAddress((void**)&xmap, g_xmap);
    cudaGetSymbolAddress((void**)&ymap, g_ymap);
    cudaGetSymbolAddress((void**)&xrt,  g_xrt);
    cudaGetSymbolAddress((void**)&yrt,  g_yrt);
    cudaGetSymbolAddress((void**)&qAT,  g_qAT);
    cudaGetSymbolAddress((void**)&qBT,  g_qBT);
    cudaGetSymbolAddress((void**)&qnA,  g_qnA);
    cudaGetSymbolAddress((void**)&qnB,  g_qnB);
    cudaGetSymbolAddress((void**)&tnY,  g_tnY);
    cudaGetSymbolAddress((void**)&tnX,  g_tnX);
    cudaGetSymbolAddress((void**)&keyA, g_keyA);
    cudaGetSymbolAddress((void**)&keyB, g_keyB);

    k_init<<<(NQ + 255) / 256, 256>>>(out);

    dim3 gg((NROWS + GBM - 1) / GBM, 2);
    k_gemm<<<gg, 256>>>(x_w, fx_w1, fx_b1, h,    NROWS, HID, XD,  1);
    k_gemm<<<gg, 256>>>(h,   fx_w2, fx_b2, xmap, NROWS, YD,  HID, 0);
    k_gemm<<<gg, 256>>>(y_w, gy_w1, gy_b1, h,    NROWS, HID, YD,  1);
    k_gemm<<<gg, 256>>>(h,   gy_w2, gy_b2, ymap, NROWS, XD,  HID, 0);
    k_gemm<<<gg, 256>>>(xmap, gy_w1, gy_b1, h,   NROWS, HID, YD,  1);
    k_gemm<<<gg, 256>>>(h,    gy_w2, gy_b2, xrt, NROWS, XD,  HID, 0);
    k_gemm<<<gg, 256>>>(ymap, fx_w1, fx_b1, h,   NROWS, HID, XD,  1);
    k_gemm<<<gg, 256>>>(h,    fx_w2, fx_b2, yrt, NROWS, YD,  HID, 0);

    k_rownorm_diff<<<(NROWS + 7) / 8, 256>>>(xrt, x_w, NROWS, XD, 1.0f / NROWS, out);
    k_rownorm_diff<<<(NROWS + 7) / 8, 256>>>(yrt, y_w, NROWS, YD, 1.0f / NROWS, out);
    k_rownorm_sup<<<(NQ + 7) / 8, 256>>>(xmap, y_w, imap, YD, 0, 1.0f / NQ, out);
    k_rownorm_sup<<<(NQ + 7) / 8, 256>>>(ymap, x_w, imap, XD, 1, 1.0f / NQ, out);

    k_tnorm<<<(NROWS + 7) / 8, 256>>>(y_w, NROWS, YD, tnY);
    k_tnorm<<<(NROWS + 7) / 8, 256>>>(x_w, NROWS, XD, tnX);
    k_gather<<<(NQ + 7) / 8, 256>>>(xmap, imap, 0, YD, KPA, qAT, qnA);
    k_gather<<<(NQ + 7) / 8, 256>>>(ymap, imap, 1, XD, KPB, qBT, qnB);

    // 19 y-chunks -> 2375 blocks ~= 4 full waves at occupancy 4 on 148 SMs
    dim3 mg(NQ / MQ, 19);
    k_mismatch<<<mg, 128>>>(qAT, qnA, y_w, tnY, keyA, NROWS, YD, KPA);
    k_mismatch<<<mg, 128>>>(qBT, qnB, x_w, tnX, keyB, NROWS, XD, KPB);

    k_finish<<<(NQ + 255) / 256, 256>>>(keyA, imap, 0, 1.0f / NQ, out);
    k_finish<<<(NQ + 255) / 256, 256>>>(keyB, imap, 1, 1.0f / NQ, out);
}